// round 14
// baseline (speedup 1.0000x reference)
#include <cuda_runtime.h>
#include <cuda_fp16.h>

#define FULLMASK 0xffffffffu

// ---------------- problem constants ----------------
#define F_IN   1433
#define HC     128          // HEADS*HID
#define NMAXN  50000
#define EMAXE  1600000
#define KPAD   1472         // 23 * 64
#define NCHUNK 23
#define NCLS   7

// ---------------- device scratch ----------------
__device__ __half g_h1preh[NMAXN * HC];        // x @ W1, fp16
__device__ float g_as1[NMAXN * 8];
__device__ float g_ad1[NMAXN * 8];
__device__ float g_h2pre[NMAXN * 8];           // h1 @ W2, padded stride 8
__device__ float g_as2[NMAXN];
__device__ float g_ad2[NMAXN];
__device__ int   g_deg[NMAXN];
__device__ int   g_off[NMAXN + 1];
__device__ int   g_cur[NMAXN];
__device__ int   g_csr[EMAXE + NMAXN];
__device__ int   g_bsum[64];
__device__ int   g_boff[64];
__device__ __half g_Wh[HC * KPAD];             // W1^T, [n][k], fp16

// ---------------- helpers ----------------
__device__ __forceinline__ void mma16816(float* c, const unsigned* a, const unsigned* b) {
    asm volatile(
        "mma.sync.aligned.m16n8k16.row.col.f32.f16.f16.f32 "
        "{%0,%1,%2,%3}, {%4,%5,%6,%7}, {%8,%9}, {%0,%1,%2,%3};"
        : "+f"(c[0]), "+f"(c[1]), "+f"(c[2]), "+f"(c[3])
        : "r"(a[0]), "r"(a[1]), "r"(a[2]), "r"(a[3]), "r"(b[0]), "r"(b[1]));
}

__device__ __forceinline__ unsigned smem_u32(const void* p) {
    unsigned a;
    asm("{ .reg .u64 t; cvta.to.shared.u64 t, %1; cvt.u32.u64 %0, t; }"
        : "=r"(a) : "l"(p));
    return a;
}

__device__ __forceinline__ void cp_async16(unsigned saddr, const void* gaddr) {
    asm volatile("cp.async.cg.shared.global [%0], [%1], 16;"
                 :: "r"(saddr), "l"(gaddr));
}
#define CP_COMMIT() asm volatile("cp.async.commit_group;" ::: "memory")
#define CP_WAIT0()  asm volatile("cp.async.wait_group 0;" ::: "memory")

__device__ __forceinline__ unsigned pack_h2(float lo, float hi) {
    __half2 h = __floats2half2_rn(lo, hi);
    return *reinterpret_cast<unsigned*>(&h);
}

// ---------------- prep: transpose W1 -> fp16 ----------------
__global__ void prep_w_kernel(const float* __restrict__ W1) {
    int idx = blockIdx.x * 256 + threadIdx.x;
    if (idx >= HC * KPAD) return;
    int n = idx / KPAD;
    int k = idx - n * KPAD;
    float v = (k < F_IN) ? W1[k * HC + n] : 0.f;
    g_Wh[idx] = __float2half_rn(v);
}

// ---------------- CSR build (edge_index is int32) ----------
__global__ void deg_init_kernel(int nn) {
    int t = blockIdx.x * 256 + threadIdx.x;
    if (t < nn) g_deg[t] = 1;  // self loop
}

__global__ void deg_count_kernel(const int* __restrict__ ei, int E, int nn) {
    int t = blockIdx.x * 256 + threadIdx.x;
    int base = t * 16;
    if (base + 15 < E) {
        #pragma unroll
        for (int j = 0; j < 4; j++) {
            int4 d = *(const int4*)(ei + E + base + j * 4);
            if ((unsigned)d.x < (unsigned)nn) atomicAdd(&g_deg[d.x], 1);
            if ((unsigned)d.y < (unsigned)nn) atomicAdd(&g_deg[d.y], 1);
            if ((unsigned)d.z < (unsigned)nn) atomicAdd(&g_deg[d.z], 1);
            if ((unsigned)d.w < (unsigned)nn) atomicAdd(&g_deg[d.w], 1);
        }
    } else {
        for (int i = base; i < E; i++) {
            int dst = ei[E + i];
            if ((unsigned)dst < (unsigned)nn) atomicAdd(&g_deg[dst], 1);
        }
    }
}

__global__ void scan1_kernel(int nn) {
    int b = blockIdx.x;
    int t = threadIdx.x;
    int idx = b * 1024 + t;
    int v = (idx < nn) ? g_deg[idx] : 0;
    int lane = t & 31, w = t >> 5;
    int s = v;
    #pragma unroll
    for (int d = 1; d < 32; d <<= 1) {
        int u = __shfl_up_sync(FULLMASK, s, d);
        if (lane >= d) s += u;
    }
    __shared__ int ws[32];
    if (lane == 31) ws[w] = s;
    __syncthreads();
    if (w == 0) {
        int x2 = ws[lane];
        #pragma unroll
        for (int d = 1; d < 32; d <<= 1) {
            int u = __shfl_up_sync(FULLMASK, x2, d);
            if (lane >= d) x2 += u;
        }
        ws[lane] = x2;
    }
    __syncthreads();
    int incl = s + ((w > 0) ? ws[w - 1] : 0);
    if (idx < nn) g_off[idx + 1] = incl;
    if (t == 1023) g_bsum[b] = incl;
}

__global__ void scan2_kernel(int nb) {
    int t = threadIdx.x;
    int v = (t < nb) ? g_bsum[t] : 0;
    int lane = t & 31, w = t >> 5;
    int s = v;
    #pragma unroll
    for (int d = 1; d < 32; d <<= 1) {
        int u = __shfl_up_sync(FULLMASK, s, d);
        if (lane >= d) s += u;
    }
    __shared__ int ws0;
    if (w == 0 && lane == 31) ws0 = s;
    __syncthreads();
    if (w == 1) s += ws0;
    if (t < 64) g_boff[t] = s - v;   // exclusive
}

__global__ void scan3_kernel(int nn) {
    int idx = blockIdx.x * 256 + threadIdx.x;
    if (idx >= nn) return;
    int add = g_boff[idx >> 10];
    int o = g_off[idx + 1] + add;
    g_off[idx + 1] = o;
    g_cur[idx] = o - g_deg[idx];
    if (idx == 0) g_off[0] = 0;
}

__global__ void scatter_kernel(const int* __restrict__ ei, int E, int nn) {
    int t = blockIdx.x * 256 + threadIdx.x;
    if (t < E) {
        int src = ei[t];
        int dst = ei[E + t];
        if ((unsigned)dst < (unsigned)nn && (unsigned)src < (unsigned)nn) {
            int pos = atomicAdd(&g_cur[dst], 1);
            g_csr[pos] = src;
        }
    } else if (t < E + nn) {
        int n = t - E;
        int pos = atomicAdd(&g_cur[n], 1);
        g_csr[pos] = n;
    }
}

// ---------------- GEMM1: h1pre = x @ W1 (fp16 HMMA, 64x128 tile, K64) ------
// CTA tile 64x128, K-chunk 64. 8 warps, each 32x32 (warp grid 2Mx4N).
// smem rows 72 halves (144B), conflict-free. A stage 9216 x2 @ 0,
// B stage 18432 x2 @ 18432. Total 55296 B; 3 CTAs/SM.
#define SROWH  72
#define AST    9216
#define BST    18432
#define GEMM1_SMEM 55296

__global__ void __launch_bounds__(256, 3) gemm1_kernel(
        const float* __restrict__ x,
        const float* __restrict__ att_s, const float* __restrict__ att_d,
        int n_rows) {
    extern __shared__ char smem[];
    unsigned sb = smem_u32(smem);

    int tid = threadIdx.x;
    int lane = tid & 31;
    int wid = tid >> 5;
    int m0 = blockIdx.x * 64;
    int mw = (wid & 1) * 32;
    int nw = (wid >> 1) * 32;
    int g = lane >> 2;
    int t4 = lane & 3;

    float acc[2][4][4];
    #pragma unroll
    for (int mi = 0; mi < 2; mi++)
        #pragma unroll
        for (int ni = 0; ni < 4; ni++)
            #pragma unroll
            for (int q = 0; q < 4; q++) acc[mi][ni][q] = 0.f;

    float xa[16];
    int rA = tid >> 5;               // 0..7 (8 rows per pass, x8 passes = 64)
    int c2A = (tid & 31) * 2;        // col pair base within 64
    int gmA = m0 + rA;
    const float* xrow = x + (size_t)gmA * F_IN;

    auto loadA = [&](int ch) {
        int k0 = ch * 64;
        #pragma unroll
        for (int i = 0; i < 8; i++) {
            int gk = k0 + c2A;
            const float* xp = xrow + (size_t)i * 8 * F_IN + gk;
            bool rv = (gmA + i * 8 < n_rows);
            xa[2 * i]     = (rv && gk < F_IN)     ? __ldg(xp)     : 0.f;
            xa[2 * i + 1] = (rv && gk + 1 < F_IN) ? __ldg(xp + 1) : 0.f;
        }
    };
    auto convA = [&](int st) {
        char* dst = smem + st * AST;
        #pragma unroll
        for (int i = 0; i < 8; i++) {
            int r = rA + i * 8;
            unsigned hp = pack_h2(xa[2 * i], xa[2 * i + 1]);
            *(unsigned*)(dst + (unsigned)(r * 144 + c2A * 2)) = hp;
        }
    };
    auto loadB = [&](int st, int ch) {
        unsigned base = sb + 2 * AST + st * BST;
        int k0 = ch * 64;
        #pragma unroll
        for (int j = 0; j < 4; j++) {
            int s = tid + 256 * j;       // 0..1023
            int r = s >> 3;
            int q = s & 7;
            cp_async16(base + (unsigned)(r * 144 + q * 16),
                       g_Wh + (size_t)r * KPAD + k0 + q * 8);
        }
        CP_COMMIT();
    };

    loadA(0);
    convA(0);
    loadB(0, 0);
    loadA(1);

    for (int ch = 0; ch < NCHUNK; ch++) {
        int st = ch & 1;
        CP_WAIT0();
        __syncthreads();

        if (ch + 1 < NCHUNK) loadB(st ^ 1, ch + 1);

        const __half* pA = (const __half*)(smem + st * AST);
        const __half* pB = (const __half*)(smem + 2 * AST + st * BST);

        #pragma unroll
        for (int kk = 0; kk < 4; kk++) {
            int kc = kk * 16 + t4 * 2;
            unsigned bh[4][2];
            #pragma unroll
            for (int ni = 0; ni < 4; ni++) {
                int bn = nw + ni * 8 + g;
                bh[ni][0] = *(const unsigned*)&pB[bn * SROWH + kc];
                bh[ni][1] = *(const unsigned*)&pB[bn * SROWH + kc + 8];
            }
            #pragma unroll
            for (int mi = 0; mi < 2; mi++) {
                int ar = mw + mi * 16 + g;
                unsigned ah[4];
                ah[0] = *(const unsigned*)&pA[ar * SROWH + kc];
                ah[1] = *(const unsigned*)&pA[(ar + 8) * SROWH + kc];
                ah[2] = *(const unsigned*)&pA[ar * SROWH + kc + 8];
                ah[3] = *(const unsigned*)&pA[(ar + 8) * SROWH + kc + 8];
                #pragma unroll
                for (int ni = 0; ni < 4; ni++)
                    mma16816(acc[mi][ni], ah, bh[ni]);
            }
        }

        if (ch + 1 < NCHUNK) {
            convA(st ^ 1);
            if (ch + 2 < NCHUNK) loadA(ch + 2);
        }
    }

    // ---- epilogue: store h1pre (fp16) + fused att dots ----
    float2 asv[4], adv[4];
    #pragma unroll
    for (int ni = 0; ni < 4; ni++) {
        int c = nw + ni * 8 + t4 * 2;
        asv[ni] = *(const float2*)(att_s + c);
        adv[ni] = *(const float2*)(att_d + c);
    }
    int h0 = nw >> 4;

    #pragma unroll
    for (int mi = 0; mi < 2; mi++) {
        int row = m0 + mw + mi * 16 + g;
        #pragma unroll
        for (int ni = 0; ni < 4; ni++) {
            int col = nw + ni * 8 + t4 * 2;
            if (row < n_rows) {
                unsigned hp = pack_h2(acc[mi][ni][0], acc[mi][ni][1]);
                *(unsigned*)(g_h1preh + (size_t)row * HC + col) = hp;
            }
            if (row + 8 < n_rows) {
                unsigned hp = pack_h2(acc[mi][ni][2], acc[mi][ni][3]);
                *(unsigned*)(g_h1preh + (size_t)(row + 8) * HC + col) = hp;
            }
        }
        float psA[2] = {0.f, 0.f}, psB[2] = {0.f, 0.f};
        float pdA[2] = {0.f, 0.f}, pdB[2] = {0.f, 0.f};
        #pragma unroll
        for (int ni = 0; ni < 4; ni++) {
            int hh = ni >> 1;
            psA[hh] += acc[mi][ni][0] * asv[ni].x + acc[mi][ni][1] * asv[ni].y;
            psB[hh] += acc[mi][ni][2] * asv[ni].x + acc[mi][ni][3] * asv[ni].y;
            pdA[hh] += acc[mi][ni][0] * adv[ni].x + acc[mi][ni][1] * adv[ni].y;
            pdB[hh] += acc[mi][ni][2] * adv[ni].x + acc[mi][ni][3] * adv[ni].y;
        }
        #pragma unroll
        for (int hh = 0; hh < 2; hh++) {
            psA[hh] += __shfl_xor_sync(FULLMASK, psA[hh], 1);
            psA[hh] += __shfl_xor_sync(FULLMASK, psA[hh], 2);
            psB[hh] += __shfl_xor_sync(FULLMASK, psB[hh], 1);
            psB[hh] += __shfl_xor_sync(FULLMASK, psB[hh], 2);
            pdA[hh] += __shfl_xor_sync(FULLMASK, pdA[hh], 1);
            pdA[hh] += __shfl_xor_sync(FULLMASK, pdA[hh], 2);
            pdB[hh] += __shfl_xor_sync(FULLMASK, pdB[hh], 1);
            pdB[hh] += __shfl_xor_sync(FULLMASK, pdB[hh], 2);
        }
        if (t4 == 0) {
            if (row < n_rows) {
                g_as1[row * 8 + h0]     = psA[0];
                g_as1[row * 8 + h0 + 1] = psA[1];
                g_ad1[row * 8 + h0]     = pdA[0];
                g_ad1[row * 8 + h0 + 1] = pdA[1];
            }
            if (row + 8 < n_rows) {
                g_as1[(row + 8) * 8 + h0]     = psB[0];
                g_as1[(row + 8) * 8 + h0 + 1] = psB[1];
                g_ad1[(row + 8) * 8 + h0]     = pdB[0];
                g_ad1[(row + 8) * 8 + h0 + 1] = pdB[1];
            }
        }
    }
}

// ---------------- agg1 (+ fused gemm2/att2): 2 warps per node --------------
// Warp pair splits the node's edge range; partials combined via smem.
__global__ void agg1_kernel(const float* __restrict__ b1,
                            const float* __restrict__ W2,
                            const float* __restrict__ as2w,
                            const float* __restrict__ ad2w, int nn) {
    __shared__ float sW[HC * NCLS];
    __shared__ float sas[NCLS], sad[NCLS];
    __shared__ float sP[4][32][5];
    for (int i = threadIdx.x; i < HC * NCLS; i += 256) sW[i] = W2[i];
    if (threadIdx.x < NCLS) {
        sas[threadIdx.x] = as2w[threadIdx.x];
        sad[threadIdx.x] = ad2w[threadIdx.x];
    }
    __syncthreads();

    int wid = threadIdx.x >> 5;
    int lane = threadIdx.x & 31;
    int slot = wid >> 1;
    int half = wid & 1;
    int node = blockIdx.x * 4 + slot;
    bool valid = node < nn;

    int s0 = 0, s1 = 0;
    if (valid) { s0 = g_off[node]; s1 = g_off[node + 1]; }
    int hme = lane >> 2;
    float adh = valid ? __ldg(g_ad1 + node * 8 + hme) : 0.f;

    int mid = s0 + ((s1 - s0 + 1) >> 1);
    int e0 = half ? mid : s0;
    int e1 = half ? s1 : mid;

    float4 acc = make_float4(0.f, 0.f, 0.f, 0.f);
    float4 acc2 = make_float4(0.f, 0.f, 0.f, 0.f);
    float z = 0.f, z2 = 0.f;
    int i = e0;
    for (; i + 2 <= e1; i += 2) {
        int sA = g_csr[i], sB = g_csr[i + 1];
        float aA = __ldg(g_as1 + sA * 8 + hme);
        float aB = __ldg(g_as1 + sB * 8 + hme);
        uint2 hA = *(const uint2*)(g_h1preh + (size_t)sA * HC + lane * 4);
        uint2 hB = *(const uint2*)(g_h1preh + (size_t)sB * HC + lane * 4);
        float tA = aA + adh, tB = aB + adh;
        float wA = __expf(fmaxf(tA, 0.2f * tA));
        float wB = __expf(fmaxf(tB, 0.2f * tB));
        z += wA; z2 += wB;
        float2 a01 = __half22float2(*(__half2*)&hA.x);
        float2 a23 = __half22float2(*(__half2*)&hA.y);
        float2 b01 = __half22float2(*(__half2*)&hB.x);
        float2 b23 = __half22float2(*(__half2*)&hB.y);
        acc.x += wA * a01.x;  acc.y += wA * a01.y;
        acc.z += wA * a23.x;  acc.w += wA * a23.y;
        acc2.x += wB * b01.x; acc2.y += wB * b01.y;
        acc2.z += wB * b23.x; acc2.w += wB * b23.y;
    }
    if (i < e1) {
        int s = g_csr[i];
        float av = __ldg(g_as1 + s * 8 + hme);
        uint2 hv = *(const uint2*)(g_h1preh + (size_t)s * HC + lane * 4);
        float tt = av + adh;
        float w = __expf(fmaxf(tt, 0.2f * tt));
        z += w;
        float2 a01 = __half22float2(*(__half2*)&hv.x);
        float2 a23 = __half22float2(*(__half2*)&hv.y);
        acc.x += w * a01.x; acc.y += w * a01.y;
        acc.z += w * a23.x; acc.w += w * a23.y;
    }
    acc.x += acc2.x; acc.y += acc2.y; acc.z += acc2.z; acc.w += acc2.w;
    z += z2;

    if (half) {
        sP[slot][lane][0] = acc.x;
        sP[slot][lane][1] = acc.y;
        sP[slot][lane][2] = acc.z;
        sP[slot][lane][3] = acc.w;
        sP[slot][lane][4] = z;
    }
    __syncthreads();
    if (half || !valid) return;

    acc.x += sP[slot][lane][0];
    acc.y += sP[slot][lane][1];
    acc.z += sP[slot][lane][2];
    acc.w += sP[slot][lane][3];
    z     += sP[slot][lane][4];

    float izh = 1.f / z;
    acc.x *= izh; acc.y *= izh; acc.z *= izh; acc.w *= izh;

    float4 bb = *(const float4*)(b1 + lane * 4);
    float t0 = acc.x + bb.x, t1 = acc.y + bb.y, t2 = acc.z + bb.z, t3 = acc.w + bb.w;
    float o0 = (t0 > 0.f) ? t0 : expm1f(t0);
    float o1 = (t1 > 0.f) ? t1 : expm1f(t1);
    float o2 = (t2 > 0.f) ? t2 : expm1f(t2);
    float o3 = (t3 > 0.f) ? t3 : expm1f(t3);

    // fused gemm2: lane holds h1 dims c..c+3; contract with W2 and reduce
    int c = lane * 4;
    float p[NCLS];
    #pragma unroll
    for (int j = 0; j < NCLS; j++) {
        p[j] = o0 * sW[(c + 0) * NCLS + j] + o1 * sW[(c + 1) * NCLS + j] +
               o2 * sW[(c + 2) * NCLS + j] + o3 * sW[(c + 3) * NCLS + j];
    }
    #pragma unroll
    for (int d = 16; d; d >>= 1) {
        #pragma unroll
        for (int j = 0; j < NCLS; j++) p[j] += __shfl_xor_sync(FULLMASK, p[j], d);
    }
    if (lane == 0) {
        float s = 0.f, dd = 0.f;
        #pragma unroll
        for (int j = 0; j < NCLS; j++) {
            g_h2pre[node * 8 + j] = p[j];
            s += p[j] * sas[j];
            dd += p[j] * sad[j];
        }
        g_h2pre[node * 8 + 7] = 0.f;
        g_as2[node] = s;
        g_ad2[node] = dd;
    }
}

// ---------------- agg2: softmax-aggregate layer 2 -> output ----------------
__global__ void agg2_kernel(const float* __restrict__ b2, float* __restrict__ out,
                            int nn) {
    int warp = (blockIdx.x * 256 + threadIdx.x) >> 5;
    int lane = threadIdx.x & 31;
    if (warp >= nn) return;
    int n = warp;
    int s0 = g_off[n], s1 = g_off[n + 1];
    float adn = g_ad2[n];

    float acc[8];
    #pragma unroll
    for (int j = 0; j < 8; j++) acc[j] = 0.f;
    float z = 0.f;
    for (int i = s0 + lane; i < s1; i += 32) {
        int s = g_csr[i];
        float t = g_as2[s] + adn;
        float e = fmaxf(t, 0.2f * t);
        float w = __expf(e);
        z += w;
        float4 v0 = *(const float4*)(g_h2pre + s * 8);
        float4 v1 = *(const float4*)(g_h2pre + s * 8 + 4);
        acc[0] += w * v0.x; acc[1] += w * v0.y;
        acc[2] += w * v0.z; acc[3] += w * v0.w;
        acc[4] += w * v1.x; acc[5] += w * v1.y;
        acc[6] += w * v1.z;
    }
    #pragma unroll
    for (int d = 16; d; d >>= 1) {
        z += __shfl_xor_sync(FULLMASK, z, d);
        #pragma unroll
        for (int j = 0; j < NCLS; j++) acc[j] += __shfl_xor_sync(FULLMASK, acc[j], d);
    }
    if (lane == 0) {
        float iz = 1.f / z;
        #pragma unroll
        for (int j = 0; j < NCLS; j++) out[n * NCLS + j] = acc[j] * iz + b2[j];
    }
}

// ---------------- launch ----------------
extern "C" void kernel_launch(void* const* d_in, const int* in_sizes, int n_in,
                              void* d_out, int out_size) {
    const float* x    = (const float*)d_in[0];
    const int*   ei   = (const int*)d_in[1];     // int32 (JAX x64 disabled)
    const float* W1   = (const float*)d_in[2];
    const float* as1w = (const float*)d_in[3];
    const float* ad1w = (const float*)d_in[4];
    const float* b1   = (const float*)d_in[5];
    const float* W2   = (const float*)d_in[6];
    const float* as2w = (const float*)d_in[7];
    const float* ad2w = (const float*)d_in[8];
    const float* b2   = (const float*)d_in[9];
    float* out = (float*)d_out;

    int nn = in_sizes[0] / F_IN;   // 50000
    int E  = in_sizes[1] / 2;      // 1600000
    int NB = (nn + 1023) / 1024;

    static cudaStream_t s_side = nullptr;
    static cudaEvent_t ev_fork = nullptr, ev_join = nullptr;
    if (s_side == nullptr) {
        cudaStreamCreateWithFlags(&s_side, cudaStreamNonBlocking);
        cudaEventCreateWithFlags(&ev_fork, cudaEventDisableTiming);
        cudaEventCreateWithFlags(&ev_join, cudaEventDisableTiming);
    }

    // fork: CSR chain on side stream, GEMM path on main (capture) stream
    cudaEventRecord(ev_fork, 0);
    cudaStreamWaitEvent(s_side, ev_fork, 0);

    deg_init_kernel<<<(nn + 255) / 256, 256, 0, s_side>>>(nn);
    deg_count_kernel<<<((E + 15) / 16 + 255) / 256, 256, 0, s_side>>>(ei, E, nn);
    scan1_kernel<<<NB, 1024, 0, s_side>>>(nn);
    scan2_kernel<<<1, 64, 0, s_side>>>(NB);
    scan3_kernel<<<(nn + 255) / 256, 256, 0, s_side>>>(nn);
    scatter_kernel<<<(E + nn + 255) / 256, 256, 0, s_side>>>(ei, E, nn);
    cudaEventRecord(ev_join, s_side);

    prep_w_kernel<<<(HC * KPAD + 255) / 256, 256>>>(W1);
    cudaFuncSetAttribute(gemm1_kernel, cudaFuncAttributeMaxDynamicSharedMemorySize,
                         GEMM1_SMEM);
    gemm1_kernel<<<(nn + 63) / 64, 256, GEMM1_SMEM>>>(x, as1w, ad1w, nn);

    cudaStreamWaitEvent(0, ev_join, 0);

    agg1_kernel<<<(nn + 3) / 4, 256>>>(b1, W2, as2w, ad2w, nn);
    int wblocks = (nn * 32 + 255) / 256;
    agg2_kernel<<<wblocks, 256>>>(b2, out, nn);
}

// round 15
// speedup vs baseline: 1.0407x; 1.0407x over previous
#include <cuda_runtime.h>
#include <cuda_fp16.h>

#define FULLMASK 0xffffffffu

// ---------------- problem constants ----------------
#define F_IN   1433
#define HC     128          // HEADS*HID
#define NMAXN  50000
#define EMAXE  1600000
#define KPAD   1472         // 23 * 64
#define NCHUNK 23
#define NCLS   7

// ---------------- device scratch ----------------
__device__ __half g_h1preh[NMAXN * HC];        // x @ W1, fp16
__device__ float g_as1[NMAXN * 8];
__device__ float g_ad1[NMAXN * 8];
__device__ float g_h2pre[NMAXN * 8];           // h1 @ W2, padded stride 8
__device__ float g_as2[NMAXN];
__device__ float g_ad2[NMAXN];
__device__ int   g_deg[NMAXN];
__device__ int   g_off[NMAXN + 1];
__device__ int   g_cur[NMAXN];
__device__ int   g_csr[EMAXE + NMAXN];
__device__ int   g_bsum[64];
__device__ int   g_boff[64];
__device__ __half g_Wh[HC * KPAD];             // W1^T, [n][k], fp16

// ---------------- helpers ----------------
__device__ __forceinline__ void mma16816(float* c, const unsigned* a, const unsigned* b) {
    asm volatile(
        "mma.sync.aligned.m16n8k16.row.col.f32.f16.f16.f32 "
        "{%0,%1,%2,%3}, {%4,%5,%6,%7}, {%8,%9}, {%0,%1,%2,%3};"
        : "+f"(c[0]), "+f"(c[1]), "+f"(c[2]), "+f"(c[3])
        : "r"(a[0]), "r"(a[1]), "r"(a[2]), "r"(a[3]), "r"(b[0]), "r"(b[1]));
}

__device__ __forceinline__ void ldsm_x4(unsigned& r0, unsigned& r1,
                                        unsigned& r2, unsigned& r3,
                                        unsigned addr) {
    asm volatile("ldmatrix.sync.aligned.m8n8.x4.shared.b16 {%0,%1,%2,%3}, [%4];"
                 : "=r"(r0), "=r"(r1), "=r"(r2), "=r"(r3) : "r"(addr));
}

__device__ __forceinline__ unsigned smem_u32(const void* p) {
    unsigned a;
    asm("{ .reg .u64 t; cvta.to.shared.u64 t, %1; cvt.u32.u64 %0, t; }"
        : "=r"(a) : "l"(p));
    return a;
}

__device__ __forceinline__ void cp_async16(unsigned saddr, const void* gaddr) {
    asm volatile("cp.async.cg.shared.global [%0], [%1], 16;"
                 :: "r"(saddr), "l"(gaddr));
}
#define CP_COMMIT() asm volatile("cp.async.commit_group;" ::: "memory")
#define CP_WAIT0()  asm volatile("cp.async.wait_group 0;" ::: "memory")

__device__ __forceinline__ unsigned pack_h2(float lo, float hi) {
    __half2 h = __floats2half2_rn(lo, hi);
    return *reinterpret_cast<unsigned*>(&h);
}

// ---------------- prep: transpose W1 -> fp16 ----------------
__global__ void prep_w_kernel(const float* __restrict__ W1) {
    int idx = blockIdx.x * 256 + threadIdx.x;
    if (idx >= HC * KPAD) return;
    int n = idx / KPAD;
    int k = idx - n * KPAD;
    float v = (k < F_IN) ? W1[k * HC + n] : 0.f;
    g_Wh[idx] = __float2half_rn(v);
}

// ---------------- CSR build (edge_index is int32) ----------
__global__ void deg_init_kernel(int nn) {
    int t = blockIdx.x * 256 + threadIdx.x;
    if (t < nn) g_deg[t] = 1;  // self loop
}

__global__ void deg_count_kernel(const int* __restrict__ ei, int E, int nn) {
    int t = blockIdx.x * 256 + threadIdx.x;
    int base = t * 16;
    if (base + 15 < E) {
        #pragma unroll
        for (int j = 0; j < 4; j++) {
            int4 d = *(const int4*)(ei + E + base + j * 4);
            if ((unsigned)d.x < (unsigned)nn) atomicAdd(&g_deg[d.x], 1);
            if ((unsigned)d.y < (unsigned)nn) atomicAdd(&g_deg[d.y], 1);
            if ((unsigned)d.z < (unsigned)nn) atomicAdd(&g_deg[d.z], 1);
            if ((unsigned)d.w < (unsigned)nn) atomicAdd(&g_deg[d.w], 1);
        }
    } else {
        for (int i = base; i < E; i++) {
            int dst = ei[E + i];
            if ((unsigned)dst < (unsigned)nn) atomicAdd(&g_deg[dst], 1);
        }
    }
}

__global__ void scan1_kernel(int nn) {
    int b = blockIdx.x;
    int t = threadIdx.x;
    int idx = b * 1024 + t;
    int v = (idx < nn) ? g_deg[idx] : 0;
    int lane = t & 31, w = t >> 5;
    int s = v;
    #pragma unroll
    for (int d = 1; d < 32; d <<= 1) {
        int u = __shfl_up_sync(FULLMASK, s, d);
        if (lane >= d) s += u;
    }
    __shared__ int ws[32];
    if (lane == 31) ws[w] = s;
    __syncthreads();
    if (w == 0) {
        int x2 = ws[lane];
        #pragma unroll
        for (int d = 1; d < 32; d <<= 1) {
            int u = __shfl_up_sync(FULLMASK, x2, d);
            if (lane >= d) x2 += u;
        }
        ws[lane] = x2;
    }
    __syncthreads();
    int incl = s + ((w > 0) ? ws[w - 1] : 0);
    if (idx < nn) g_off[idx + 1] = incl;
    if (t == 1023) g_bsum[b] = incl;
}

__global__ void scan2_kernel(int nb) {
    int t = threadIdx.x;
    int v = (t < nb) ? g_bsum[t] : 0;
    int lane = t & 31, w = t >> 5;
    int s = v;
    #pragma unroll
    for (int d = 1; d < 32; d <<= 1) {
        int u = __shfl_up_sync(FULLMASK, s, d);
        if (lane >= d) s += u;
    }
    __shared__ int ws0;
    if (w == 0 && lane == 31) ws0 = s;
    __syncthreads();
    if (w == 1) s += ws0;
    if (t < 64) g_boff[t] = s - v;   // exclusive
}

__global__ void scan3_kernel(int nn) {
    int idx = blockIdx.x * 256 + threadIdx.x;
    if (idx >= nn) return;
    int add = g_boff[idx >> 10];
    int o = g_off[idx + 1] + add;
    g_off[idx + 1] = o;
    g_cur[idx] = o - g_deg[idx];
    if (idx == 0) g_off[0] = 0;
}

__global__ void scatter_kernel(const int* __restrict__ ei, int E, int nn) {
    int t = blockIdx.x * 256 + threadIdx.x;
    if (t < E) {
        int src = ei[t];
        int dst = ei[E + t];
        if ((unsigned)dst < (unsigned)nn && (unsigned)src < (unsigned)nn) {
            int pos = atomicAdd(&g_cur[dst], 1);
            g_csr[pos] = src;
        }
    } else if (t < E + nn) {
        int n = t - E;
        int pos = atomicAdd(&g_cur[n], 1);
        g_csr[pos] = n;
    }
}

// ---------------- GEMM1: h1pre = x @ W1 (fp16 HMMA, ldmatrix fragments) ----
// CTA tile 64x128, K-chunk 64. 8 warps, each 32x32 (warp grid 2Mx4N).
// smem rows 72 halves (144B), conflict-free for STS and LDSM.
#define SROWH  72
#define AST    9216
#define BST    18432
#define GEMM1_SMEM 55296

__global__ void __launch_bounds__(256, 3) gemm1_kernel(
        const float* __restrict__ x,
        const float* __restrict__ att_s, const float* __restrict__ att_d,
        int n_rows) {
    extern __shared__ char smem[];
    unsigned sb = smem_u32(smem);

    int tid = threadIdx.x;
    int lane = tid & 31;
    int wid = tid >> 5;
    int m0 = blockIdx.x * 64;
    int mw = (wid & 1) * 32;
    int nw = (wid >> 1) * 32;
    int g = lane >> 2;
    int t4 = lane & 3;

    // ldmatrix lane-address components (loop invariant)
    unsigned lrow = (lane & 7) + ((lane >> 3) & 1) * 8;   // 0..15
    unsigned lcol = (lane >> 4) * 16;                     // 0 or 16 bytes

    float acc[2][4][4];
    #pragma unroll
    for (int mi = 0; mi < 2; mi++)
        #pragma unroll
        for (int ni = 0; ni < 4; ni++)
            #pragma unroll
            for (int q = 0; q < 4; q++) acc[mi][ni][q] = 0.f;

    float xa[16];
    int rA = tid >> 5;               // 0..7 (8 rows per pass, x8 passes = 64)
    int c2A = (tid & 31) * 2;        // col pair base within 64
    int gmA = m0 + rA;
    const float* xrow = x + (size_t)gmA * F_IN;

    auto loadA = [&](int ch) {
        int k0 = ch * 64;
        #pragma unroll
        for (int i = 0; i < 8; i++) {
            int gk = k0 + c2A;
            const float* xp = xrow + (size_t)i * 8 * F_IN + gk;
            bool rv = (gmA + i * 8 < n_rows);
            xa[2 * i]     = (rv && gk < F_IN)     ? __ldg(xp)     : 0.f;
            xa[2 * i + 1] = (rv && gk + 1 < F_IN) ? __ldg(xp + 1) : 0.f;
        }
    };
    auto convA = [&](int st) {
        char* dst = smem + st * AST;
        #pragma unroll
        for (int i = 0; i < 8; i++) {
            int r = rA + i * 8;
            unsigned hp = pack_h2(xa[2 * i], xa[2 * i + 1]);
            *(unsigned*)(dst + (unsigned)(r * 144 + c2A * 2)) = hp;
        }
    };
    auto loadB = [&](int st, int ch) {
        unsigned base = sb + 2 * AST + st * BST;
        int k0 = ch * 64;
        #pragma unroll
        for (int j = 0; j < 4; j++) {
            int s = tid + 256 * j;       // 0..1023
            int r = s >> 3;
            int q = s & 7;
            cp_async16(base + (unsigned)(r * 144 + q * 16),
                       g_Wh + (size_t)r * KPAD + k0 + q * 8);
        }
        CP_COMMIT();
    };

    loadA(0);
    convA(0);
    loadB(0, 0);
    loadA(1);

    for (int ch = 0; ch < NCHUNK; ch++) {
        int st = ch & 1;
        CP_WAIT0();
        __syncthreads();

        if (ch + 1 < NCHUNK) loadB(st ^ 1, ch + 1);

        unsigned baseA = sb + st * AST;
        unsigned baseB = sb + 2 * AST + st * BST;
        unsigned aAddr0 = baseA + (mw + lrow) * 144 + lcol;
        unsigned aAddr1 = baseA + (mw + 16 + lrow) * 144 + lcol;
        unsigned bAddr0 = baseB + (nw + lrow) * 144 + lcol;
        unsigned bAddr1 = baseB + (nw + 16 + lrow) * 144 + lcol;

        #pragma unroll
        for (int kk = 0; kk < 4; kk++) {
            unsigned ko = (unsigned)(kk * 32);
            unsigned ah[2][4], bh[4][2];
            ldsm_x4(ah[0][0], ah[0][1], ah[0][2], ah[0][3], aAddr0 + ko);
            ldsm_x4(ah[1][0], ah[1][1], ah[1][2], ah[1][3], aAddr1 + ko);
            ldsm_x4(bh[0][0], bh[1][0], bh[0][1], bh[1][1], bAddr0 + ko);
            ldsm_x4(bh[2][0], bh[3][0], bh[2][1], bh[3][1], bAddr1 + ko);
            #pragma unroll
            for (int mi = 0; mi < 2; mi++)
                #pragma unroll
                for (int ni = 0; ni < 4; ni++)
                    mma16816(acc[mi][ni], ah[mi], bh[ni]);
        }

        if (ch + 1 < NCHUNK) {
            convA(st ^ 1);
            if (ch + 2 < NCHUNK) loadA(ch + 2);
        }
    }

    // ---- epilogue: store h1pre (fp16) + fused att dots ----
    float2 asv[4], adv[4];
    #pragma unroll
    for (int ni = 0; ni < 4; ni++) {
        int c = nw + ni * 8 + t4 * 2;
        asv[ni] = *(const float2*)(att_s + c);
        adv[ni] = *(const float2*)(att_d + c);
    }
    int h0 = nw >> 4;

    #pragma unroll
    for (int mi = 0; mi < 2; mi++) {
        int row = m0 + mw + mi * 16 + g;
        #pragma unroll
        for (int ni = 0; ni < 4; ni++) {
            int col = nw + ni * 8 + t4 * 2;
            if (row < n_rows) {
                unsigned hp = pack_h2(acc[mi][ni][0], acc[mi][ni][1]);
                *(unsigned*)(g_h1preh + (size_t)row * HC + col) = hp;
            }
            if (row + 8 < n_rows) {
                unsigned hp = pack_h2(acc[mi][ni][2], acc[mi][ni][3]);
                *(unsigned*)(g_h1preh + (size_t)(row + 8) * HC + col) = hp;
            }
        }
        float psA[2] = {0.f, 0.f}, psB[2] = {0.f, 0.f};
        float pdA[2] = {0.f, 0.f}, pdB[2] = {0.f, 0.f};
        #pragma unroll
        for (int ni = 0; ni < 4; ni++) {
            int hh = ni >> 1;
            psA[hh] += acc[mi][ni][0] * asv[ni].x + acc[mi][ni][1] * asv[ni].y;
            psB[hh] += acc[mi][ni][2] * asv[ni].x + acc[mi][ni][3] * asv[ni].y;
            pdA[hh] += acc[mi][ni][0] * adv[ni].x + acc[mi][ni][1] * adv[ni].y;
            pdB[hh] += acc[mi][ni][2] * adv[ni].x + acc[mi][ni][3] * adv[ni].y;
        }
        #pragma unroll
        for (int hh = 0; hh < 2; hh++) {
            psA[hh] += __shfl_xor_sync(FULLMASK, psA[hh], 1);
            psA[hh] += __shfl_xor_sync(FULLMASK, psA[hh], 2);
            psB[hh] += __shfl_xor_sync(FULLMASK, psB[hh], 1);
            psB[hh] += __shfl_xor_sync(FULLMASK, psB[hh], 2);
            pdA[hh] += __shfl_xor_sync(FULLMASK, pdA[hh], 1);
            pdA[hh] += __shfl_xor_sync(FULLMASK, pdA[hh], 2);
            pdB[hh] += __shfl_xor_sync(FULLMASK, pdB[hh], 1);
            pdB[hh] += __shfl_xor_sync(FULLMASK, pdB[hh], 2);
        }
        if (t4 == 0) {
            if (row < n_rows) {
                g_as1[row * 8 + h0]     = psA[0];
                g_as1[row * 8 + h0 + 1] = psA[1];
                g_ad1[row * 8 + h0]     = pdA[0];
                g_ad1[row * 8 + h0 + 1] = pdA[1];
            }
            if (row + 8 < n_rows) {
                g_as1[(row + 8) * 8 + h0]     = psB[0];
                g_as1[(row + 8) * 8 + h0 + 1] = psB[1];
                g_ad1[(row + 8) * 8 + h0]     = pdB[0];
                g_ad1[(row + 8) * 8 + h0 + 1] = pdB[1];
            }
        }
    }
}

// ---------------- agg1 (+ fused gemm2/att2): 2 warps per node --------------
__global__ void agg1_kernel(const float* __restrict__ b1,
                            const float* __restrict__ W2,
                            const float* __restrict__ as2w,
                            const float* __restrict__ ad2w, int nn) {
    __shared__ float sW[HC * NCLS];
    __shared__ float sas[NCLS], sad[NCLS];
    __shared__ float sP[4][32][5];
    for (int i = threadIdx.x; i < HC * NCLS; i += 256) sW[i] = W2[i];
    if (threadIdx.x < NCLS) {
        sas[threadIdx.x] = as2w[threadIdx.x];
        sad[threadIdx.x] = ad2w[threadIdx.x];
    }
    __syncthreads();

    int wid = threadIdx.x >> 5;
    int lane = threadIdx.x & 31;
    int slot = wid >> 1;
    int half = wid & 1;
    int node = blockIdx.x * 4 + slot;
    bool valid = node < nn;

    int s0 = 0, s1 = 0;
    if (valid) { s0 = g_off[node]; s1 = g_off[node + 1]; }
    int hme = lane >> 2;
    float adh = valid ? __ldg(g_ad1 + node * 8 + hme) : 0.f;

    int mid = s0 + ((s1 - s0 + 1) >> 1);
    int e0 = half ? mid : s0;
    int e1 = half ? s1 : mid;

    float4 acc = make_float4(0.f, 0.f, 0.f, 0.f);
    float4 acc2 = make_float4(0.f, 0.f, 0.f, 0.f);
    float z = 0.f, z2 = 0.f;
    int i = e0;
    for (; i + 2 <= e1; i += 2) {
        int sA = g_csr[i], sB = g_csr[i + 1];
        float aA = __ldg(g_as1 + sA * 8 + hme);
        float aB = __ldg(g_as1 + sB * 8 + hme);
        uint2 hA = *(const uint2*)(g_h1preh + (size_t)sA * HC + lane * 4);
        uint2 hB = *(const uint2*)(g_h1preh + (size_t)sB * HC + lane * 4);
        float tA = aA + adh, tB = aB + adh;
        float wA = __expf(fmaxf(tA, 0.2f * tA));
        float wB = __expf(fmaxf(tB, 0.2f * tB));
        z += wA; z2 += wB;
        float2 a01 = __half22float2(*(__half2*)&hA.x);
        float2 a23 = __half22float2(*(__half2*)&hA.y);
        float2 b01 = __half22float2(*(__half2*)&hB.x);
        float2 b23 = __half22float2(*(__half2*)&hB.y);
        acc.x += wA * a01.x;  acc.y += wA * a01.y;
        acc.z += wA * a23.x;  acc.w += wA * a23.y;
        acc2.x += wB * b01.x; acc2.y += wB * b01.y;
        acc2.z += wB * b23.x; acc2.w += wB * b23.y;
    }
    if (i < e1) {
        int s = g_csr[i];
        float av = __ldg(g_as1 + s * 8 + hme);
        uint2 hv = *(const uint2*)(g_h1preh + (size_t)s * HC + lane * 4);
        float tt = av + adh;
        float w = __expf(fmaxf(tt, 0.2f * tt));
        z += w;
        float2 a01 = __half22float2(*(__half2*)&hv.x);
        float2 a23 = __half22float2(*(__half2*)&hv.y);
        acc.x += w * a01.x; acc.y += w * a01.y;
        acc.z += w * a23.x; acc.w += w * a23.y;
    }
    acc.x += acc2.x; acc.y += acc2.y; acc.z += acc2.z; acc.w += acc2.w;
    z += z2;

    if (half) {
        sP[slot][lane][0] = acc.x;
        sP[slot][lane][1] = acc.y;
        sP[slot][lane][2] = acc.z;
        sP[slot][lane][3] = acc.w;
        sP[slot][lane][4] = z;
    }
    __syncthreads();
    if (half || !valid) return;

    acc.x += sP[slot][lane][0];
    acc.y += sP[slot][lane][1];
    acc.z += sP[slot][lane][2];
    acc.w += sP[slot][lane][3];
    z     += sP[slot][lane][4];

    float izh = 1.f / z;
    acc.x *= izh; acc.y *= izh; acc.z *= izh; acc.w *= izh;

    float4 bb = *(const float4*)(b1 + lane * 4);
    float t0 = acc.x + bb.x, t1 = acc.y + bb.y, t2 = acc.z + bb.z, t3 = acc.w + bb.w;
    float o0 = (t0 > 0.f) ? t0 : expm1f(t0);
    float o1 = (t1 > 0.f) ? t1 : expm1f(t1);
    float o2 = (t2 > 0.f) ? t2 : expm1f(t2);
    float o3 = (t3 > 0.f) ? t3 : expm1f(t3);

    // fused gemm2: lane holds h1 dims c..c+3; contract with W2 and reduce
    int c = lane * 4;
    float p[NCLS];
    #pragma unroll
    for (int j = 0; j < NCLS; j++) {
        p[j] = o0 * sW[(c + 0) * NCLS + j] + o1 * sW[(c + 1) * NCLS + j] +
               o2 * sW[(c + 2) * NCLS + j] + o3 * sW[(c + 3) * NCLS + j];
    }
    #pragma unroll
    for (int d = 16; d; d >>= 1) {
        #pragma unroll
        for (int j = 0; j < NCLS; j++) p[j] += __shfl_xor_sync(FULLMASK, p[j], d);
    }
    if (lane == 0) {
        float s = 0.f, dd = 0.f;
        #pragma unroll
        for (int j = 0; j < NCLS; j++) {
            g_h2pre[node * 8 + j] = p[j];
            s += p[j] * sas[j];
            dd += p[j] * sad[j];
        }
        g_h2pre[node * 8 + 7] = 0.f;
        g_as2[node] = s;
        g_ad2[node] = dd;
    }
}

// ---------------- agg2: softmax-aggregate layer 2 -> output ----------------
__global__ void agg2_kernel(const float* __restrict__ b2, float* __restrict__ out,
                            int nn) {
    int warp = (blockIdx.x * 256 + threadIdx.x) >> 5;
    int lane = threadIdx.x & 31;
    if (warp >= nn) return;
    int n = warp;
    int s0 = g_off[n], s1 = g_off[n + 1];
    float adn = g_ad2[n];

    float acc[8];
    #pragma unroll
    for (int j = 0; j < 8; j++) acc[j] = 0.f;
    float z = 0.f;
    for (int i = s0 + lane; i < s1; i += 32) {
        int s = g_csr[i];
        float t = g_as2[s] + adn;
        float e = fmaxf(t, 0.2f * t);
        float w = __expf(e);
        z += w;
        float4 v0 = *(const float4*)(g_h2pre + s * 8);
        float4 v1 = *(const float4*)(g_h2pre + s * 8 + 4);
        acc[0] += w * v0.x; acc[1] += w * v0.y;
        acc[2] += w * v0.z; acc[3] += w * v0.w;
        acc[4] += w * v1.x; acc[5] += w * v1.y;
        acc[6] += w * v1.z;
    }
    #pragma unroll
    for (int d = 16; d; d >>= 1) {
        z += __shfl_xor_sync(FULLMASK, z, d);
        #pragma unroll
        for (int j = 0; j < NCLS; j++) acc[j] += __shfl_xor_sync(FULLMASK, acc[j], d);
    }
    if (lane == 0) {
        float iz = 1.f / z;
        #pragma unroll
        for (int j = 0; j < NCLS; j++) out[n * NCLS + j] = acc[j] * iz + b2[j];
    }
}

// ---------------- launch ----------------
extern "C" void kernel_launch(void* const* d_in, const int* in_sizes, int n_in,
                              void* d_out, int out_size) {
    const float* x    = (const float*)d_in[0];
    const int*   ei   = (const int*)d_in[1];     // int32 (JAX x64 disabled)
    const float* W1   = (const float*)d_in[2];
    const float* as1w = (const float*)d_in[3];
    const float* ad1w = (const float*)d_in[4];
    const float* b1   = (const float*)d_in[5];
    const float* W2   = (const float*)d_in[6];
    const float* as2w = (const float*)d_in[7];
    const float* ad2w = (const float*)d_in[8];
    const float* b2   = (const float*)d_in[9];
    float* out = (float*)d_out;

    int nn = in_sizes[0] / F_IN;   // 50000
    int E  = in_sizes[1] / 2;      // 1600000
    int NB = (nn + 1023) / 1024;

    static cudaStream_t s_side = nullptr;
    static cudaEvent_t ev_fork = nullptr, ev_join = nullptr;
    if (s_side == nullptr) {
        cudaStreamCreateWithFlags(&s_side, cudaStreamNonBlocking);
        cudaEventCreateWithFlags(&ev_fork, cudaEventDisableTiming);
        cudaEventCreateWithFlags(&ev_join, cudaEventDisableTiming);
    }

    // fork: CSR chain on side stream, GEMM path on main (capture) stream
    cudaEventRecord(ev_fork, 0);
    cudaStreamWaitEvent(s_side, ev_fork, 0);

    deg_init_kernel<<<(nn + 255) / 256, 256, 0, s_side>>>(nn);
    deg_count_kernel<<<((E + 15) / 16 + 255) / 256, 256, 0, s_side>>>(ei, E, nn);
    scan1_kernel<<<NB, 1024, 0, s_side>>>(nn);
    scan2_kernel<<<1, 64, 0, s_side>>>(NB);
    scan3_kernel<<<(nn + 255) / 256, 256, 0, s_side>>>(nn);
    scatter_kernel<<<(E + nn + 255) / 256, 256, 0, s_side>>>(ei, E, nn);
    cudaEventRecord(ev_join, s_side);

    prep_w_kernel<<<(HC * KPAD + 255) / 256, 256>>>(W1);
    cudaFuncSetAttribute(gemm1_kernel, cudaFuncAttributeMaxDynamicSharedMemorySize,
                         GEMM1_SMEM);
    gemm1_kernel<<<(nn + 63) / 64, 256, GEMM1_SMEM>>>(x, as1w, ad1w, nn);

    cudaStreamWaitEvent(0, ev_join, 0);

    agg1_kernel<<<(nn + 3) / 4, 256>>>(b1, W2, as2w, ad2w, nn);
    int wblocks = (nn * 32 + 255) / 256;
    agg2_kernel<<<wblocks, 256>>>(b2, out, nn);
}